// round 6
// baseline (speedup 1.0000x reference)
#include <cuda_runtime.h>
#include <math_constants.h>

#define N_POINTS 50000
#define CHANNELS 64
#define CAP 128   // bucket capacity per point; counts ~Poisson(32), max ~66

// Static scratch (no allocations allowed). __device__ globals are
// zero-initialized at module load; segmax_kernel restores d_cursor to zero
// after consuming it, so the invariant "cursors are zero at kernel_launch
// entry" holds for the correctness call, capture call, and every replay.
__device__ int d_cursor[N_POINTS];
__device__ int d_bucket[N_POINTS * CAP];   // 25.6 MB, 512B-aligned rows

// ---------------------------------------------------------------------------
// K2: bucket-build. One thread per TWO edges (int4 index load): claim a slot
// in the destination point's bucket, record the source index. 1.6M atomics.
// On overflow (cursor past CAP) the slot write is skipped — the cursor value
// itself signals K3 to take the exact slow path for that point.
// ---------------------------------------------------------------------------
__device__ __forceinline__ void bucket_one(int o_idx, int i_idx) {
    int pos = atomicAdd(&d_cursor[o_idx], 1);
    if (pos < CAP) {
        d_bucket[o_idx * CAP + pos] = i_idx;
    }
}

__global__ void bucket_kernel(const int* __restrict__ idx, int n_edges) {
    int t = blockIdx.x * blockDim.x + threadIdx.x;
    int e0 = t * 2;
    if (e0 >= n_edges) return;

    if (e0 + 1 < n_edges) {
        int4 q = __ldg(reinterpret_cast<const int4*>(idx) + t);
        bucket_one(q.x, q.y);
        bucket_one(q.z, q.w);
    } else {
        int2 pr = __ldg(reinterpret_cast<const int2*>(idx) + e0);
        bucket_one(pr.x, pr.y);
    }
}

// ---------------------------------------------------------------------------
// K3: dense segment-max. 16 lanes per point, one float4 (4 channels) per lane.
// Coalesced 256B row gathers from the L2-resident feature table; max entirely
// in registers; write-only store to out (covers every point, incl. empty
// segments -> -inf). Afterwards resets d_cursor[p] = 0 for the next call.
// Overflowed points (cnt > CAP, probability ~e^-100) fall back to an exact
// full-edge-list rescan, idempotent under max.
// ---------------------------------------------------------------------------
__device__ __forceinline__ float4 max4(float4 a, float4 b) {
    return make_float4(fmaxf(a.x, b.x), fmaxf(a.y, b.y),
                       fmaxf(a.z, b.z), fmaxf(a.w, b.w));
}

// N_POINTS*16 must be an exact multiple of the block size: no early-exit
// lanes, so full-mask __syncwarp below is safe.
static_assert((N_POINTS * 16) % 256 == 0, "grid must be exact");

__global__ void segmax_kernel(const float* __restrict__ feat,
                              const int* __restrict__ idx,
                              float* __restrict__ out,
                              int n_edges) {
    int t = blockIdx.x * blockDim.x + threadIdx.x;
    int p = t >> 4;
    int c4 = (t & 15) << 2;

    int cnt_raw = d_cursor[p];
    int cnt = cnt_raw > CAP ? CAP : cnt_raw;
    const int* bkt = d_bucket + p * CAP;   // 512B-aligned

    float4 acc = make_float4(-CUDART_INF_F, -CUDART_INF_F, -CUDART_INF_F, -CUDART_INF_F);

    int i = 0;
    // 4 indices per LDG (int4), 4 independent feature-row chains in flight.
    for (; i + 4 <= cnt; i += 4) {
        int4 s = __ldg(reinterpret_cast<const int4*>(bkt + i));
        float4 v0 = *reinterpret_cast<const float4*>(feat + (long long)s.x * CHANNELS + c4);
        float4 v1 = *reinterpret_cast<const float4*>(feat + (long long)s.y * CHANNELS + c4);
        float4 v2 = *reinterpret_cast<const float4*>(feat + (long long)s.z * CHANNELS + c4);
        float4 v3 = *reinterpret_cast<const float4*>(feat + (long long)s.w * CHANNELS + c4);
        acc = max4(acc, max4(max4(v0, v1), max4(v2, v3)));
    }
    for (; i < cnt; i++) {
        int s = __ldg(bkt + i);
        float4 v = *reinterpret_cast<const float4*>(feat + (long long)s * CHANNELS + c4);
        acc = max4(acc, v);
    }

    // Exactness guard: bucket overflowed -> rescan all edges for this point.
    // Idempotent under max; probability of taking this branch is ~0.
    if (cnt_raw > CAP) {
        for (int e = 0; e < n_edges; e++) {
            int2 pr = __ldg(reinterpret_cast<const int2*>(idx) + e);
            if (pr.x == p) {
                float4 v = *reinterpret_cast<const float4*>(feat + (long long)pr.y * CHANNELS + c4);
                acc = max4(acc, v);
            }
        }
    }

    *reinterpret_cast<float4*>(out + (long long)p * CHANNELS + c4) = acc;

    // Self-clean: restore the zero-cursor invariant for the next call.
    // All 16 lanes of this point have read cnt above; fence via __syncwarp
    // (full mask is safe: grid is exact, no early exits).
    __syncwarp();
    if (c4 == 0) d_cursor[p] = 0;
}

extern "C" void kernel_launch(void* const* d_in, const int* in_sizes, int n_in,
                              void* d_out, int out_size) {
    const float* feat = (const float*)d_in[0];   // [N_POINTS, 64] f32
    const int* idx = (const int*)d_in[1];        // [N_EDGES, 2] i32
    float* out = (float*)d_out;                  // [N_POINTS, 64] f32

    int n_edges = in_sizes[1] / 2;

    // K2: bucket build (2 edges / thread)
    int nt2 = (n_edges + 1) / 2;
    bucket_kernel<<<(nt2 + 255) / 256, 256>>>(idx, n_edges);

    // K3: dense per-point max (16 lanes/point) + cursor self-reset
    segmax_kernel<<<(N_POINTS * 16) / 256, 256>>>(feat, idx, out, n_edges);
}

// round 7
// speedup vs baseline: 1.2242x; 1.2242x over previous
#include <cuda_runtime.h>
#include <math_constants.h>

#define N_POINTS 50000
#define CHANNELS 64
#define CAP 128           // bucket capacity per point; counts ~Poisson(32), max ~66
#define OVF_CAP (1 << 20) // overflow list capacity (expected usage: 0)

// Static scratch (no allocations). __device__ globals are zero-initialized at
// module load; segmax_kernel restores all counters to zero after consuming
// them, so the zero-invariant holds for the correctness call, the capture
// call, and every graph replay.
__device__ int d_cursor[N_POINTS];
__device__ int d_bucket[N_POINTS * CAP];   // 25.6 MB, 512B-aligned rows
__device__ int d_ovf_count;
__device__ int d_ovf_list[OVF_CAP];        // edge ids that exceeded CAP
__device__ int d_done;                     // K3 block-arrival counter

// ---------------------------------------------------------------------------
// K2: bucket-build. One thread per TWO edges (int4 index load): claim a slot
// in the destination point's bucket, record the source index. 1.6M atomics.
// Edges whose bucket is full go to the overflow list (folded into K3).
// ---------------------------------------------------------------------------
__device__ __forceinline__ void bucket_one(int e, int o_idx, int i_idx) {
    int pos = atomicAdd(&d_cursor[o_idx], 1);
    if (pos < CAP) {
        d_bucket[o_idx * CAP + pos] = i_idx;
    } else {
        int op = atomicAdd(&d_ovf_count, 1);
        if (op < OVF_CAP) d_ovf_list[op] = e;
    }
}

__global__ void bucket_kernel(const int* __restrict__ idx, int n_edges) {
    int t = blockIdx.x * blockDim.x + threadIdx.x;
    int e0 = t * 2;
    if (e0 >= n_edges) return;

    if (e0 + 1 < n_edges) {
        int4 q = __ldg(reinterpret_cast<const int4*>(idx) + t);
        bucket_one(e0,     q.x, q.y);
        bucket_one(e0 + 1, q.z, q.w);
    } else {
        int2 pr = __ldg(reinterpret_cast<const int2*>(idx) + e0);
        bucket_one(e0, pr.x, pr.y);
    }
}

// ---------------------------------------------------------------------------
// K3: dense segment-max (body identical to the 54.4us R5 winner) + self-clean
// epilogue that removes the need for a separate init kernel.
// 16 lanes per point, one float4 (4 channels) per lane. Coalesced 256B row
// gathers from the L2-resident feature table; max in registers; write-only
// store (covers empty segments -> -inf). Overflow edges (expected: none) are
// folded in via a guarded scan of the compact overflow list.
// ---------------------------------------------------------------------------
__device__ __forceinline__ float4 max4(float4 a, float4 b) {
    return make_float4(fmaxf(a.x, b.x), fmaxf(a.y, b.y),
                       fmaxf(a.z, b.z), fmaxf(a.w, b.w));
}

// Exact grid: N_POINTS*16 threads, 256/block -> no early exits, __syncthreads
// in the epilogue is safe.
static_assert((N_POINTS * 16) % 256 == 0, "grid must be exact");

__global__ void segmax_kernel(const float* __restrict__ feat,
                              const int* __restrict__ idx,
                              float* __restrict__ out) {
    int t = blockIdx.x * blockDim.x + threadIdx.x;
    int p = t >> 4;
    int c4 = (t & 15) << 2;

    int cnt = d_cursor[p];
    if (cnt > CAP) cnt = CAP;
    const int* bkt = d_bucket + p * CAP;   // 512B-aligned

    float4 acc = make_float4(-CUDART_INF_F, -CUDART_INF_F, -CUDART_INF_F, -CUDART_INF_F);

    int i = 0;
    // 4 indices per LDG (int4), 4 independent feature-row chains in flight.
    for (; i + 4 <= cnt; i += 4) {
        int4 s = __ldg(reinterpret_cast<const int4*>(bkt + i));
        float4 v0 = *reinterpret_cast<const float4*>(feat + (long long)s.x * CHANNELS + c4);
        float4 v1 = *reinterpret_cast<const float4*>(feat + (long long)s.y * CHANNELS + c4);
        float4 v2 = *reinterpret_cast<const float4*>(feat + (long long)s.z * CHANNELS + c4);
        float4 v3 = *reinterpret_cast<const float4*>(feat + (long long)s.w * CHANNELS + c4);
        acc = max4(acc, max4(max4(v0, v1), max4(v2, v3)));
    }
    for (; i < cnt; i++) {
        int s = __ldg(bkt + i);
        float4 v = *reinterpret_cast<const float4*>(feat + (long long)s * CHANNELS + c4);
        acc = max4(acc, v);
    }

    // Exactness guard: fold in any overflow edges targeting this point.
    // One L2-hot broadcast load; branch ~never taken.
    int ovf = d_ovf_count;
    if (ovf > 0) {
        if (ovf > OVF_CAP) ovf = OVF_CAP;
        for (int j = 0; j < ovf; j++) {
            int e = d_ovf_list[j];
            int2 pr = __ldg(reinterpret_cast<const int2*>(idx) + e);
            if (pr.x == p) {
                float4 v = *reinterpret_cast<const float4*>(feat + (long long)pr.y * CHANNELS + c4);
                acc = max4(acc, v);
            }
        }
    }

    *reinterpret_cast<float4*>(out + (long long)p * CHANNELS + c4) = acc;

    // --- Self-clean epilogue (replaces the init kernel) ---
    __syncthreads();                       // everyone in block done reading
    if ((t & 15) == 0) d_cursor[p] = 0;    // one lane per point
    if (threadIdx.x == 0) {
        __threadfence();
        int old = atomicAdd(&d_done, 1);
        if (old == gridDim.x - 1) {        // last block: all reads of
            d_ovf_count = 0;               // d_ovf_count already happened
            d_done = 0;
        }
    }
}

extern "C" void kernel_launch(void* const* d_in, const int* in_sizes, int n_in,
                              void* d_out, int out_size) {
    const float* feat = (const float*)d_in[0];   // [N_POINTS, 64] f32
    const int* idx = (const int*)d_in[1];        // [N_EDGES, 2] i32
    float* out = (float*)d_out;                  // [N_POINTS, 64] f32

    int n_edges = in_sizes[1] / 2;

    // K2: bucket build (2 edges / thread)
    int nt2 = (n_edges + 1) / 2;
    bucket_kernel<<<(nt2 + 255) / 256, 256>>>(idx, n_edges);

    // K3: dense per-point max (16 lanes/point) + self-clean
    segmax_kernel<<<(N_POINTS * 16) / 256, 256>>>(feat, idx, out);
}